// round 2
// baseline (speedup 1.0000x reference)
#include <cuda_runtime.h>

#define DM   1024
#define NH   16
#define HD   64
#define BSZ  4
#define SEQ  2048
#define MTOT (BSZ * SEQ)   // 8192

// Scratch (no cudaMalloc allowed): 4 x 32MB fp32
__device__ float g_q[BSZ * NH * SEQ * HD];
__device__ float g_k[BSZ * NH * SEQ * HD];
__device__ float g_v[BSZ * NH * SEQ * HD];
__device__ float g_attn[MTOT * DM];

// ---------------------------------------------------------------------------
// C = A @ W^T + bias.  A: [MTOT, DM] row-major, W: [DM, DM] row-major (NT GEMM,
// both operands K-contiguous). 64x64 tile, kt=16, 256 threads, 4x4 per thread.
// MODE 0: scatter output to [B, H, S, HD] (n-tile == one head)
// MODE 1: plain row-major [MTOT, DM]
// ---------------------------------------------------------------------------
template <int MODE>
__global__ __launch_bounds__(256) void gemm_nt(const float* __restrict__ A,
                                               const float* __restrict__ W,
                                               const float* __restrict__ bias,
                                               float* __restrict__ C) {
    __shared__ float As[16][64];   // k-major
    __shared__ float Ws[16][64];   // k-major
    const int m0  = blockIdx.x * 64;
    const int n0  = blockIdx.y * 64;
    const int tid = threadIdx.x;
    const int tx  = tid & 15;        // n direction
    const int ty  = tid >> 4;        // m direction
    const int lr  = tid >> 2;        // load row 0..63
    const int lc  = (tid & 3) * 4;   // load col 0,4,8,12

    const float* Ap = A + (size_t)(m0 + lr) * DM + lc;
    const float* Wp = W + (size_t)(n0 + lr) * DM + lc;

    float acc[4][4] = {};

    float4 av = *(const float4*)Ap;
    float4 wv = *(const float4*)Wp;

    for (int k0 = 0; k0 < DM; k0 += 16) {
        As[lc + 0][lr] = av.x; As[lc + 1][lr] = av.y;
        As[lc + 2][lr] = av.z; As[lc + 3][lr] = av.w;
        Ws[lc + 0][lr] = wv.x; Ws[lc + 1][lr] = wv.y;
        Ws[lc + 2][lr] = wv.z; Ws[lc + 3][lr] = wv.w;
        __syncthreads();
        if (k0 + 16 < DM) {   // prefetch next k-tile while computing
            av = *(const float4*)(Ap + k0 + 16);
            wv = *(const float4*)(Wp + k0 + 16);
        }
#pragma unroll
        for (int kk = 0; kk < 16; kk++) {
            float a[4], w[4];
            *(float4*)a = *(const float4*)&As[kk][ty * 4];
            *(float4*)w = *(const float4*)&Ws[kk][tx * 4];
#pragma unroll
            for (int i = 0; i < 4; i++)
#pragma unroll
                for (int j = 0; j < 4; j++)
                    acc[i][j] = fmaf(a[i], w[j], acc[i][j]);
        }
        __syncthreads();
    }

    float bb[4];
    *(float4*)bb = *(const float4*)&bias[n0 + tx * 4];

#pragma unroll
    for (int i = 0; i < 4; i++) {
        const int m = m0 + ty * 4 + i;
        float4 v;
        v.x = acc[i][0] + bb[0];
        v.y = acc[i][1] + bb[1];
        v.z = acc[i][2] + bb[2];
        v.w = acc[i][3] + bb[3];
        if (MODE == 0) {
            const int b = m >> 11;           // m / SEQ
            const int s = m & (SEQ - 1);
            const int h = blockIdx.y;        // n-tile width 64 == HD
            float* dst = C + ((size_t)((b * NH + h) * SEQ + s)) * HD + tx * 4;
            *(float4*)dst = v;
        } else {
            *(float4*)(C + (size_t)m * DM + n0 + tx * 4) = v;
        }
    }
}

// ---------------------------------------------------------------------------
// Flash attention, fp32, per-block: one (b*NH+h, 64-row q tile).
// Qt/Kt stored d-major (transposed) for conflict-free float4 reads in the
// score GEMM; P reuses Kt's buffer (dead after scores) for the PV GEMM.
// Static smem = 3 * 64 * 64 * 4B = 48KB exactly.
// ---------------------------------------------------------------------------
__global__ __launch_bounds__(256) void flash_attn(const float* __restrict__ gq,
                                                  const float* __restrict__ gk,
                                                  const float* __restrict__ gv,
                                                  float* __restrict__ out) {
    __shared__ float Qt[64 * 64];    // Qt[d*64 + q]
    __shared__ float KPt[64 * 64];   // phase 1: Kt[d*64 + k]; phase 2: Pt[k*64 + q]
    __shared__ float Vs[64 * 64];    // Vs[k*64 + c]

    const int qt  = blockIdx.x;      // 0..31
    const int bh  = blockIdx.y;      // 0..63
    const int tid = threadIdx.x;
    const int tx  = tid & 15;
    const int ty  = tid >> 4;

    const float* qbase = gq + ((size_t)bh * SEQ + qt * 64) * HD;
    const float* kbase = gk + (size_t)bh * SEQ * HD;
    const float* vbase = gv + (size_t)bh * SEQ * HD;

    // Load Q tile, transposed into smem
#pragma unroll
    for (int u = 0; u < 4; u++) {
        const int f    = tid + u * 256;      // float4 index 0..1023
        const int row  = f >> 4;             // 16 float4 per 64-wide row
        const int colf = (f & 15) * 4;
        float4 v = *(const float4*)(qbase + (size_t)row * HD + colf);
        Qt[(colf + 0) * 64 + row] = v.x;
        Qt[(colf + 1) * 64 + row] = v.y;
        Qt[(colf + 2) * 64 + row] = v.z;
        Qt[(colf + 3) * 64 + row] = v.w;
    }

    float o[4][4]  = {};
    float mi[4]    = {-1e30f, -1e30f, -1e30f, -1e30f};
    float li[4]    = {};

    for (int j0 = 0; j0 < SEQ; j0 += 64) {
        // Stage K/V tile into registers before syncing
        float4 kf[4], vf[4];
#pragma unroll
        for (int u = 0; u < 4; u++) {
            const int f    = tid + u * 256;
            const int row  = f >> 4;
            const int colf = (f & 15) * 4;
            kf[u] = *(const float4*)(kbase + (size_t)(j0 + row) * HD + colf);
            vf[u] = *(const float4*)(vbase + (size_t)(j0 + row) * HD + colf);
        }
        __syncthreads();   // previous iteration's PV reads complete
#pragma unroll
        for (int u = 0; u < 4; u++) {
            const int f    = tid + u * 256;
            const int row  = f >> 4;
            const int colf = (f & 15) * 4;
            KPt[(colf + 0) * 64 + row] = kf[u].x;
            KPt[(colf + 1) * 64 + row] = kf[u].y;
            KPt[(colf + 2) * 64 + row] = kf[u].z;
            KPt[(colf + 3) * 64 + row] = kf[u].w;
            *(float4*)&Vs[row * 64 + colf] = vf[u];
        }
        __syncthreads();   // tiles visible

        // Scores: S = Q K^T  (read d-major Qt, Kt)
        float s[4][4] = {};
#pragma unroll 8
        for (int d = 0; d < 64; d++) {
            float qa[4], kb[4];
            *(float4*)qa = *(const float4*)&Qt[d * 64 + ty * 4];
            *(float4*)kb = *(const float4*)&KPt[d * 64 + tx * 4];
#pragma unroll
            for (int i = 0; i < 4; i++)
#pragma unroll
                for (int j = 0; j < 4; j++)
                    s[i][j] = fmaf(qa[i], kb[j], s[i][j]);
        }

        // Online softmax update (row reductions across the 16-lane tx group)
#pragma unroll
        for (int i = 0; i < 4; i++) {
            float rm = -1e30f;
#pragma unroll
            for (int j = 0; j < 4; j++) {
                s[i][j] *= 0.125f;   // 1/sqrt(HD)
                rm = fmaxf(rm, s[i][j]);
            }
#pragma unroll
            for (int off = 8; off > 0; off >>= 1)
                rm = fmaxf(rm, __shfl_xor_sync(0xffffffffu, rm, off));
            const float mnew = fmaxf(mi[i], rm);
            const float corr = __expf(mi[i] - mnew);
            float rs = 0.0f;
#pragma unroll
            for (int j = 0; j < 4; j++) {
                s[i][j] = __expf(s[i][j] - mnew);
                rs += s[i][j];
            }
#pragma unroll
            for (int off = 8; off > 0; off >>= 1)
                rs += __shfl_xor_sync(0xffffffffu, rs, off);
            li[i] = li[i] * corr + rs;
            mi[i] = mnew;
#pragma unroll
            for (int j = 0; j < 4; j++) o[i][j] *= corr;
        }

        __syncthreads();   // all Kt reads done; safe to overwrite with P
#pragma unroll
        for (int j = 0; j < 4; j++)
#pragma unroll
            for (int i = 0; i < 4; i++)
                KPt[(tx * 4 + j) * 64 + ty * 4 + i] = s[i][j];   // Pt[k][q]
        __syncthreads();   // P visible

        // O += P @ V
#pragma unroll 8
        for (int k = 0; k < 64; k++) {
            float p[4], vv[4];
            *(float4*)p  = *(const float4*)&KPt[k * 64 + ty * 4];
            *(float4*)vv = *(const float4*)&Vs[k * 64 + tx * 4];
#pragma unroll
            for (int i = 0; i < 4; i++)
#pragma unroll
                for (int j = 0; j < 4; j++)
                    o[i][j] = fmaf(p[i], vv[j], o[i][j]);
        }
    }

    // Epilogue: normalize, write to [B, S, D] layout for the output projection
    const int b = bh >> 4;
    const int h = bh & 15;
#pragma unroll
    for (int i = 0; i < 4; i++) {
        const float inv = 1.0f / li[i];
        const int q = qt * 64 + ty * 4 + i;
        float4 v;
        v.x = o[i][0] * inv;
        v.y = o[i][1] * inv;
        v.z = o[i][2] * inv;
        v.w = o[i][3] * inv;
        *(float4*)(out + ((size_t)(b * SEQ + q)) * DM + h * HD + tx * 4) = v;
    }
}

// ---------------------------------------------------------------------------
extern "C" void kernel_launch(void* const* d_in, const int* in_sizes, int n_in,
                              void* d_out, int out_size) {
    (void)in_sizes; (void)n_in; (void)out_size;
    const float* Q  = (const float*)d_in[0];
    const float* K  = (const float*)d_in[1];
    const float* V  = (const float*)d_in[2];
    const float* Wq = (const float*)d_in[3];
    const float* bq = (const float*)d_in[4];
    const float* Wk = (const float*)d_in[5];
    const float* bk = (const float*)d_in[6];
    const float* Wv = (const float*)d_in[7];
    const float* bv = (const float*)d_in[8];
    const float* Wo = (const float*)d_in[9];
    const float* bo = (const float*)d_in[10];

    float *gq, *gk, *gv, *ga;
    cudaGetSymbolAddress((void**)&gq, g_q);
    cudaGetSymbolAddress((void**)&gk, g_k);
    cudaGetSymbolAddress((void**)&gv, g_v);
    cudaGetSymbolAddress((void**)&ga, g_attn);

    dim3 ggrid(MTOT / 64, DM / 64);
    gemm_nt<0><<<ggrid, 256>>>(Q, Wq, bq, gq);
    gemm_nt<0><<<ggrid, 256>>>(K, Wk, bk, gk);
    gemm_nt<0><<<ggrid, 256>>>(V, Wv, bv, gv);

    flash_attn<<<dim3(SEQ / 64, BSZ * NH), 256>>>(gq, gk, gv, ga);

    gemm_nt<1><<<ggrid, 256>>>(ga, Wo, bo, (float*)d_out);
}

// round 3
// speedup vs baseline: 2.1661x; 2.1661x over previous
#include <cuda_runtime.h>

#define DM   1024
#define NH   16
#define HD   64
#define BSZ  4
#define SEQ  2048
#define MTOT (BSZ * SEQ)   // 8192

// Scratch (no cudaMalloc allowed)
__device__ float g_q[BSZ * NH * SEQ * HD];      // [B,H,S,Dh]
__device__ float g_k[BSZ * NH * SEQ * HD];      // [B,H,Dh,S]  (pre-transposed!)
__device__ float g_v[BSZ * NH * SEQ * HD];      // [B,H,S,Dh]
__device__ float g_attn[MTOT * DM];             // [B,S,D]

// ---------------------------------------------------------------------------
// Wide NT GEMM: C = A @ W^T + bias. 64m x 128n tile, kt=16, 256 thr, 4x8/thread.
// FMA-bound inner loop: 3 LDS.128 (48B) per 32 FFMA.
// MODE 0: scatter to [B,H,S,Dh] (n-tile covers heads 2*by, 2*by+1)
// MODE 1: row-major [MTOT, DM]
// ---------------------------------------------------------------------------
template <int MODE>
__global__ __launch_bounds__(256) void gemm_wide(const float* __restrict__ A,
                                                 const float* __restrict__ W,
                                                 const float* __restrict__ bias,
                                                 float* __restrict__ C) {
    __shared__ float As[16][64];    // k-major
    __shared__ float Ws[16][128];   // k-major
    const int m0  = blockIdx.x * 64;
    const int n0  = blockIdx.y * 128;
    const int tid = threadIdx.x;
    const int tx  = tid & 15;        // n direction
    const int ty  = tid >> 4;        // m direction
    const int lr  = tid >> 2;        // load row 0..63
    const int lc  = (tid & 3) * 4;   // load col 0,4,8,12

    const float* Ap  = A + (size_t)(m0 + lr) * DM + lc;
    const float* Wp0 = W + (size_t)(n0 + lr) * DM + lc;
    const float* Wp1 = W + (size_t)(n0 + 64 + lr) * DM + lc;

    float acc[4][8] = {};

    float4 av  = *(const float4*)Ap;
    float4 wv0 = *(const float4*)Wp0;
    float4 wv1 = *(const float4*)Wp1;

    for (int k0 = 0; k0 < DM; k0 += 16) {
        As[lc + 0][lr] = av.x;  As[lc + 1][lr] = av.y;
        As[lc + 2][lr] = av.z;  As[lc + 3][lr] = av.w;
        Ws[lc + 0][lr] = wv0.x; Ws[lc + 1][lr] = wv0.y;
        Ws[lc + 2][lr] = wv0.z; Ws[lc + 3][lr] = wv0.w;
        Ws[lc + 0][64 + lr] = wv1.x; Ws[lc + 1][64 + lr] = wv1.y;
        Ws[lc + 2][64 + lr] = wv1.z; Ws[lc + 3][64 + lr] = wv1.w;
        __syncthreads();
        if (k0 + 16 < DM) {
            av  = *(const float4*)(Ap + k0 + 16);
            wv0 = *(const float4*)(Wp0 + k0 + 16);
            wv1 = *(const float4*)(Wp1 + k0 + 16);
        }
#pragma unroll
        for (int kk = 0; kk < 16; kk++) {
            float a[4], w[8];
            *(float4*)a       = *(const float4*)&As[kk][ty * 4];
            *(float4*)w       = *(const float4*)&Ws[kk][tx * 4];
            *(float4*)(w + 4) = *(const float4*)&Ws[kk][64 + tx * 4];
#pragma unroll
            for (int i = 0; i < 4; i++)
#pragma unroll
                for (int j = 0; j < 8; j++)
                    acc[i][j] = fmaf(a[i], w[j], acc[i][j]);
        }
        __syncthreads();
    }

    float bb[8];
    *(float4*)bb       = *(const float4*)&bias[n0 + tx * 4];
    *(float4*)(bb + 4) = *(const float4*)&bias[n0 + 64 + tx * 4];

#pragma unroll
    for (int i = 0; i < 4; i++) {
        const int m = m0 + ty * 4 + i;
        float4 v0, v1;
        v0.x = acc[i][0] + bb[0]; v0.y = acc[i][1] + bb[1];
        v0.z = acc[i][2] + bb[2]; v0.w = acc[i][3] + bb[3];
        v1.x = acc[i][4] + bb[4]; v1.y = acc[i][5] + bb[5];
        v1.z = acc[i][6] + bb[6]; v1.w = acc[i][7] + bb[7];
        if (MODE == 0) {
            const int b = m >> 11;
            const int s = m & (SEQ - 1);
            const int h0 = blockIdx.y * 2;
            float* d0 = C + ((size_t)((b * NH + h0) * SEQ + s)) * HD + tx * 4;
            float* d1 = C + ((size_t)((b * NH + h0 + 1) * SEQ + s)) * HD + tx * 4;
            *(float4*)d0 = v0;
            *(float4*)d1 = v1;
        } else {
            *(float4*)(C + (size_t)m * DM + n0 + tx * 4)      = v0;
            *(float4*)(C + (size_t)m * DM + n0 + 64 + tx * 4) = v1;
        }
    }
}

// ---------------------------------------------------------------------------
// K projection GEMM with TRANSPOSED output: writes K as [B,H,Dh,S].
// 64x64 tile (n-tile == one head), smem-transpose epilogue, coalesced stores.
// ---------------------------------------------------------------------------
__global__ __launch_bounds__(256) void gemm_k_t(const float* __restrict__ A,
                                                const float* __restrict__ W,
                                                const float* __restrict__ bias,
                                                float* __restrict__ C) {
    __shared__ float As[16][64];
    __shared__ float Ws[16][64];
    __shared__ float Tr[64][65];     // [d][s_local], pad 65 (scalar reads)
    const int m0  = blockIdx.x * 64;
    const int n0  = blockIdx.y * 64;
    const int tid = threadIdx.x;
    const int tx  = tid & 15;
    const int ty  = tid >> 4;
    const int lr  = tid >> 2;
    const int lc  = (tid & 3) * 4;

    const float* Ap = A + (size_t)(m0 + lr) * DM + lc;
    const float* Wp = W + (size_t)(n0 + lr) * DM + lc;

    float acc[4][4] = {};
    float4 av = *(const float4*)Ap;
    float4 wv = *(const float4*)Wp;

    for (int k0 = 0; k0 < DM; k0 += 16) {
        As[lc + 0][lr] = av.x; As[lc + 1][lr] = av.y;
        As[lc + 2][lr] = av.z; As[lc + 3][lr] = av.w;
        Ws[lc + 0][lr] = wv.x; Ws[lc + 1][lr] = wv.y;
        Ws[lc + 2][lr] = wv.z; Ws[lc + 3][lr] = wv.w;
        __syncthreads();
        if (k0 + 16 < DM) {
            av = *(const float4*)(Ap + k0 + 16);
            wv = *(const float4*)(Wp + k0 + 16);
        }
#pragma unroll
        for (int kk = 0; kk < 16; kk++) {
            float a[4], w[4];
            *(float4*)a = *(const float4*)&As[kk][ty * 4];
            *(float4*)w = *(const float4*)&Ws[kk][tx * 4];
#pragma unroll
            for (int i = 0; i < 4; i++)
#pragma unroll
                for (int j = 0; j < 4; j++)
                    acc[i][j] = fmaf(a[i], w[j], acc[i][j]);
        }
        __syncthreads();
    }

    float bb[4];
    *(float4*)bb = *(const float4*)&bias[n0 + tx * 4];

    // Transpose through smem: Tr[d=n_local][s=m_local]
#pragma unroll
    for (int i = 0; i < 4; i++)
#pragma unroll
        for (int j = 0; j < 4; j++)
            Tr[tx * 4 + j][ty * 4 + i] = acc[i][j] + bb[j];
    __syncthreads();

    const int b  = m0 >> 11;
    const int s0 = m0 & (SEQ - 1);
    const int h  = blockIdx.y;
    const int r  = tid >> 2;           // d row 0..63
    const int cg = (tid & 3) * 16;     // s col group
    float* dst = C + ((size_t)((b * NH + h) * HD + r)) * SEQ + s0;
#pragma unroll
    for (int u = 0; u < 4; u++) {
        const int c = cg + u * 4;
        float4 t;
        t.x = Tr[r][c + 0]; t.y = Tr[r][c + 1];
        t.z = Tr[r][c + 2]; t.w = Tr[r][c + 3];
        *(float4*)(dst + c) = t;
    }
}

// ---------------------------------------------------------------------------
// Flash attention, fp32. K comes pre-transposed [B,H,Dh,S] -> zero-conflict
// float4 tile staging. P is stored q-major (conflict-free float4 stores).
// Smem = 48KB exactly, 4 CTAs/SM.
// ---------------------------------------------------------------------------
__global__ __launch_bounds__(256) void flash_attn(const float* __restrict__ gq,
                                                  const float* __restrict__ gkt,
                                                  const float* __restrict__ gv,
                                                  float* __restrict__ out) {
    __shared__ float Qt[64 * 64];    // Qt[d*64 + q]
    __shared__ float KP[64 * 64];    // phase 1: Kt[d*64 + k]; phase 2: P[q*64 + k]
    __shared__ float Vs[64 * 64];    // Vs[k*64 + d]

    const int qt  = blockIdx.x;
    const int bh  = blockIdx.y;
    const int tid = threadIdx.x;
    const int tx  = tid & 15;
    const int ty  = tid >> 4;

    const float* qbase  = gq  + ((size_t)bh * SEQ + qt * 64) * HD;
    const float* ktbase = gkt + (size_t)bh * HD * SEQ;    // [d][s]
    const float* vbase  = gv  + (size_t)bh * SEQ * HD;

    // Load Q tile transposed (one-time; conflicts amortized over 32 iters)
#pragma unroll
    for (int u = 0; u < 4; u++) {
        const int f    = tid + u * 256;
        const int row  = f >> 4;
        const int colf = (f & 15) * 4;
        float4 v = *(const float4*)(qbase + (size_t)row * HD + colf);
        Qt[(colf + 0) * 64 + row] = v.x;
        Qt[(colf + 1) * 64 + row] = v.y;
        Qt[(colf + 2) * 64 + row] = v.z;
        Qt[(colf + 3) * 64 + row] = v.w;
    }

    float o[4][4] = {};
    float mi[4]   = {-1e30f, -1e30f, -1e30f, -1e30f};
    float li[4]   = {};

    for (int j0 = 0; j0 < SEQ; j0 += 64) {
        // Stage K^T and V tiles into registers (both row-major float4, coalesced)
        float4 kf[4], vf[4];
#pragma unroll
        for (int u = 0; u < 4; u++) {
            const int f    = tid + u * 256;
            const int row  = f >> 4;
            const int colf = (f & 15) * 4;
            kf[u] = *(const float4*)(ktbase + (size_t)row * SEQ + j0 + colf);
            vf[u] = *(const float4*)(vbase + (size_t)(j0 + row) * HD + colf);
        }
        __syncthreads();   // previous iteration's PV reads complete
#pragma unroll
        for (int u = 0; u < 4; u++) {
            const int f    = tid + u * 256;
            const int row  = f >> 4;
            const int colf = (f & 15) * 4;
            *(float4*)&KP[row * 64 + colf] = kf[u];   // Kt[d][k], conflict-free
            *(float4*)&Vs[row * 64 + colf] = vf[u];   // V[k][d],  conflict-free
        }
        __syncthreads();

        // Scores: S = Q K^T
        float s[4][4] = {};
#pragma unroll 8
        for (int d = 0; d < 64; d++) {
            float qa[4], kb[4];
            *(float4*)qa = *(const float4*)&Qt[d * 64 + ty * 4];
            *(float4*)kb = *(const float4*)&KP[d * 64 + tx * 4];
#pragma unroll
            for (int i = 0; i < 4; i++)
#pragma unroll
                for (int j = 0; j < 4; j++)
                    s[i][j] = fmaf(qa[i], kb[j], s[i][j]);
        }

        // Online softmax (reduction across 16-lane tx group)
#pragma unroll
        for (int i = 0; i < 4; i++) {
            float rm = -1e30f;
#pragma unroll
            for (int j = 0; j < 4; j++) {
                s[i][j] *= 0.125f;
                rm = fmaxf(rm, s[i][j]);
            }
#pragma unroll
            for (int off = 8; off > 0; off >>= 1)
                rm = fmaxf(rm, __shfl_xor_sync(0xffffffffu, rm, off));
            const float mnew = fmaxf(mi[i], rm);
            const float corr = __expf(mi[i] - mnew);
            float rs = 0.0f;
#pragma unroll
            for (int j = 0; j < 4; j++) {
                s[i][j] = __expf(s[i][j] - mnew);
                rs += s[i][j];
            }
#pragma unroll
            for (int off = 8; off > 0; off >>= 1)
                rs += __shfl_xor_sync(0xffffffffu, rs, off);
            li[i] = li[i] * corr + rs;
            mi[i] = mnew;
#pragma unroll
            for (int j = 0; j < 4; j++) o[i][j] *= corr;
        }

        __syncthreads();   // Kt reads done; overwrite KP with P (q-major)
#pragma unroll
        for (int i = 0; i < 4; i++) {
            float4 ps;
            ps.x = s[i][0]; ps.y = s[i][1]; ps.z = s[i][2]; ps.w = s[i][3];
            *(float4*)&KP[(ty * 4 + i) * 64 + tx * 4] = ps;   // conflict-free
        }
        __syncthreads();

        // O += P @ V : P read float4 along k (broadcast), V float4 along d
#pragma unroll 4
        for (int k0 = 0; k0 < 64; k0 += 4) {
            float p[4][4];
#pragma unroll
            for (int i = 0; i < 4; i++)
                *(float4*)p[i] = *(const float4*)&KP[(ty * 4 + i) * 64 + k0];
#pragma unroll
            for (int kk = 0; kk < 4; kk++) {
                float vv[4];
                *(float4*)vv = *(const float4*)&Vs[(k0 + kk) * 64 + tx * 4];
#pragma unroll
                for (int i = 0; i < 4; i++)
#pragma unroll
                    for (int j = 0; j < 4; j++)
                        o[i][j] = fmaf(p[i][kk], vv[j], o[i][j]);
            }
        }
    }

    // Epilogue: normalize, write [B,S,D] for the output projection
    const int b = bh >> 4;
    const int h = bh & 15;
#pragma unroll
    for (int i = 0; i < 4; i++) {
        const float inv = 1.0f / li[i];
        const int q = qt * 64 + ty * 4 + i;
        float4 v;
        v.x = o[i][0] * inv;
        v.y = o[i][1] * inv;
        v.z = o[i][2] * inv;
        v.w = o[i][3] * inv;
        *(float4*)(out + ((size_t)(b * SEQ + q)) * DM + h * HD + tx * 4) = v;
    }
}

// ---------------------------------------------------------------------------
extern "C" void kernel_launch(void* const* d_in, const int* in_sizes, int n_in,
                              void* d_out, int out_size) {
    (void)in_sizes; (void)n_in; (void)out_size;
    const float* Q  = (const float*)d_in[0];
    const float* K  = (const float*)d_in[1];
    const float* V  = (const float*)d_in[2];
    const float* Wq = (const float*)d_in[3];
    const float* bq = (const float*)d_in[4];
    const float* Wk = (const float*)d_in[5];
    const float* bk = (const float*)d_in[6];
    const float* Wv = (const float*)d_in[7];
    const float* bv = (const float*)d_in[8];
    const float* Wo = (const float*)d_in[9];
    const float* bo = (const float*)d_in[10];

    float *gq, *gk, *gv, *ga;
    cudaGetSymbolAddress((void**)&gq, g_q);
    cudaGetSymbolAddress((void**)&gk, g_k);
    cudaGetSymbolAddress((void**)&gv, g_v);
    cudaGetSymbolAddress((void**)&ga, g_attn);

    dim3 gw(MTOT / 64, DM / 128);   // wide GEMM grid
    dim3 gk64(MTOT / 64, DM / 64);  // K-transposed GEMM grid

    gemm_wide<0><<<gw, 256>>>(Q, Wq, bq, gq);
    gemm_k_t<<<gk64, 256>>>(K, Wk, bk, gk);
    gemm_wide<0><<<gw, 256>>>(V, Wv, bv, gv);

    flash_attn<<<dim3(SEQ / 64, BSZ * NH), 256>>>(gq, gk, gv, ga);

    gemm_wide<1><<<gw, 256>>>(ga, Wo, bo, (float*)d_out);
}